// round 4
// baseline (speedup 1.0000x reference)
#include <cuda_runtime.h>
#include <cuda_bf16.h>

// AngularSymmetryMod: out[b,i,p] = 2^{1-zeta} * sum_{j,k} (1 + lambda_p*cos(theta_ijk - th_p))^4
//                                   * exp(-ita*((Rij+Rik)/2 - Rs_p)^2) * f_ij * f_ik
// theta_ijk = (vec_ij . vec_ik) / (Rij*Rik + 1e-5),  vec_ij = x_i - x_j
// p = lambda_idx*20 + Rs_idx*4 + theta_idx   (np.meshgrid 'xy': shape (1,2,1,5,4) -> flatten)
//
// One block per (b,i). j<=k triangular pairs, weight 2 off-diagonal (all factors j/k-symmetric).
// cos(theta - th) computed literally as cosf(fl32(theta - th)) so the argument bit-matches
// the reference's fp32 subtraction at large theta (theta = dot/(Rj*Rk+1e-5) can reach ~1e5).
// Grid = 512 blocks, all resident in one wave (<= 148 SMs * 4 CTA).

#define TPB 128
#define NATOM 32
#define NPAIR (NATOM * (NATOM + 1) / 2)   // 528

__global__ __launch_bounds__(TPB)
void angsym_kernel(const float* __restrict__ dcut,
                   const float* __restrict__ dmat,
                   const float* __restrict__ coords,
                   float* __restrict__ out)
{
    const int bi = blockIdx.x;             // 0..511
    const int b = bi >> 5;
    const int i = bi & 31;

    __shared__ float vx[NATOM], vy[NATOM], vz[NATOM], Rr[NATOM], Ff[NATOM];
    __shared__ float red[4][40];

    const int t = threadIdx.x;

    const float cix = coords[(b * NATOM + i) * 3 + 0];
    const float ciy = coords[(b * NATOM + i) * 3 + 1];
    const float ciz = coords[(b * NATOM + i) * 3 + 2];

    if (t < NATOM) {
        const int j = t;
        vx[j] = cix - coords[(b * NATOM + j) * 3 + 0];
        vy[j] = ciy - coords[(b * NATOM + j) * 3 + 1];
        vz[j] = ciz - coords[(b * NATOM + j) * 3 + 2];
        Rr[j] = dmat[(b * NATOM + i) * NATOM + j];
        Ff[j] = dcut[(b * NATOM + i) * NATOM + j];
    }
    __syncthreads();

    // Rs = {0.5,1.17,1.83,2.5,3.17}/BOHR  (double-evaluated, rounds like np f64->f32)
    const float Rs[5] = {
        (float)(0.5  / 0.52917721092),
        (float)(1.17 / 0.52917721092),
        (float)(1.83 / 0.52917721092),
        (float)(2.5  / 0.52917721092),
        (float)(3.17 / 0.52917721092)
    };
    // theta shifts as fp32 literals, subtracted in fp32 exactly like the reference
    const float TH[4] = { 0.0f, 1.57f, 3.14f, 4.71f };

    float acc[40];
#pragma unroll
    for (int p = 0; p < 40; ++p) acc[p] = 0.0f;

    for (int p = t; p < NPAIR; p += TPB) {
        // decode triangular pair index: p = k*(k+1)/2 + j, j <= k.
        // 8p+1 <= 4217 is exact in fp32; sqrtf is correctly rounded, so k0 is
        // within 1 of true k. One predicated correction each way suffices.
        int k = (int)((sqrtf(8.0f * (float)p + 1.0f) - 1.0f) * 0.5f);
        if ((k + 1) * (k + 2) / 2 <= p) ++k;
        if (k * (k + 1) / 2 > p) --k;
        const int j = p - k * (k + 1) / 2;

        const float Rj = Rr[j], Rk = Rr[k];
        const float dot = vx[j] * vx[k] + vy[j] * vy[k] + vz[j] * vz[k];
        const float theta = dot / (Rj * Rk + 1e-5f);

        const float avg = 0.5f * (Rj + Rk);
        const float w = Ff[j] * Ff[k] * ((j != k) ? 2.0f : 1.0f);

        float rad[5];
#pragma unroll
        for (int r = 0; r < 5; ++r) {
            const float u = avg - Rs[r];
            rad[r] = __expf(-1.12f * u * u) * w;
        }

#pragma unroll
        for (int tt = 0; tt < 4; ++tt) {
            // accurate cosf of the fp32-rounded (theta - th): bit-matches reference arg
            const float ca = cosf(theta - TH[tt]);
            const float ap = 1.0f + ca;
            const float am = 1.0f - ca;
            const float ap2 = ap * ap;
            const float am2 = am * am;
            const float angp = ap2 * ap2;                   // (1+c)^4  (lambda=+1)
            const float angm = am2 * am2;                   // (1-c)^4  (lambda=-1)
#pragma unroll
            for (int r = 0; r < 5; ++r) {
                acc[r * 4 + tt]      = fmaf(angp, rad[r], acc[r * 4 + tt]);
                acc[20 + r * 4 + tt] = fmaf(angm, rad[r], acc[20 + r * 4 + tt]);
            }
        }
    }

    // warp reduce each of the 40 accumulators
#pragma unroll
    for (int p = 0; p < 40; ++p) {
        float v = acc[p];
        v += __shfl_down_sync(0xffffffffu, v, 16);
        v += __shfl_down_sync(0xffffffffu, v, 8);
        v += __shfl_down_sync(0xffffffffu, v, 4);
        v += __shfl_down_sync(0xffffffffu, v, 2);
        v += __shfl_down_sync(0xffffffffu, v, 1);
        acc[p] = v;
    }

    const int warp = t >> 5, lane = t & 31;
    if (lane == 0) {
#pragma unroll
        for (int p = 0; p < 40; ++p) red[warp][p] = acc[p];
    }
    __syncthreads();

    if (t < 40) {
        const float v = red[0][t] + red[1][t] + red[2][t] + red[3][t];
        out[bi * 40 + t] = 0.125f * v;   // 2^{1-zeta} = 0.125
    }
}

extern "C" void kernel_launch(void* const* d_in, const int* in_sizes, int n_in,
                              void* d_out, int out_size)
{
    const float* dcut   = (const float*)d_in[0];  // d_cutoff (16,32,32)
    const float* dmat   = (const float*)d_in[1];  // d        (16,32,32)
    const float* coords = (const float*)d_in[2];  // atom_coordinates (16,32,3)
    float* out = (float*)d_out;                   // (16,32,40)
    (void)in_sizes; (void)n_in; (void)out_size;

    angsym_kernel<<<512, TPB>>>(dcut, dmat, coords, out);
}